// round 8
// baseline (speedup 1.0000x reference)
#include <cuda_runtime.h>
#include <cstdint>

// Problem constants (fixed by the dataset)
#define BB 4
#define NN 10000
#define EE 163840
#define NREG 2000
#define DIN 64
#define DEN 16
#define NEG_SLOPE 0.2f

// ---------------- static device scratch (no allocations allowed) -------------
__device__ float g_h[BB * NN * DEN];              // h = x @ W
__device__ float g_as[BB * NN];                   // h @ att_src
__device__ float g_ad[BB * NN];                   // h @ att_dst
__device__ float g_den[BB * NN];                  // softmax denominator per dst
__device__ __align__(16) float g_rep[BB * NN * DEN]; // unnormalized then final rep
__device__ int   g_rowstart[BB * (NREG + 1)];     // CSR row starts over sorted src
__device__ float g_ce;                            // lin_edge . att_edge (scalar)

// ---------------- K1: per-node h = xW, a_s, a_d; zero den/rep; g_ce ----------
__global__ void k_node(const float* __restrict__ x, const float* __restrict__ W,
                       const float* __restrict__ att_s, const float* __restrict__ att_d,
                       const float* __restrict__ lin_edge, const float* __restrict__ att_edge) {
    __shared__ float Ws[DIN * DEN];
    for (int i = threadIdx.x; i < DIN * DEN; i += blockDim.x) Ws[i] = W[i];
    __syncthreads();

    int t = blockIdx.x * blockDim.x + threadIdx.x;
    if (t == 0) {
        float c = 0.0f;
#pragma unroll
        for (int j = 0; j < DEN; j++) c += lin_edge[j] * att_edge[j];
        g_ce = c;
    }
    if (t >= BB * NN) return;

    // zero the accumulators the edge pass will atomically update
    g_den[t] = 0.0f;
    float4* rz = reinterpret_cast<float4*>(g_rep + (size_t)t * DEN);
    float4 z4 = make_float4(0.f, 0.f, 0.f, 0.f);
#pragma unroll
    for (int u = 0; u < DEN / 4; u++) rz[u] = z4;

    const float4* xr = reinterpret_cast<const float4*>(x + (size_t)t * DIN);
    float acc[DEN];
#pragma unroll
    for (int c = 0; c < DEN; c++) acc[c] = 0.0f;

#pragma unroll
    for (int k4 = 0; k4 < DIN / 4; k4++) {
        float4 v = xr[k4];
        const float* w0 = &Ws[(k4 * 4 + 0) * DEN];
        const float* w1 = &Ws[(k4 * 4 + 1) * DEN];
        const float* w2 = &Ws[(k4 * 4 + 2) * DEN];
        const float* w3 = &Ws[(k4 * 4 + 3) * DEN];
#pragma unroll
        for (int c = 0; c < DEN; c++)
            acc[c] += v.x * w0[c] + v.y * w1[c] + v.z * w2[c] + v.w * w3[c];
    }

    float as = 0.0f, ad = 0.0f;
#pragma unroll
    for (int c = 0; c < DEN; c++) {
        as += acc[c] * __ldg(&att_s[c]);
        ad += acc[c] * __ldg(&att_d[c]);
    }

    float4* hp = reinterpret_cast<float4*>(g_h + (size_t)t * DEN);
#pragma unroll
    for (int u = 0; u < DEN / 4; u++)
        hp[u] = make_float4(acc[u * 4 + 0], acc[u * 4 + 1], acc[u * 4 + 2], acc[u * 4 + 3]);
    g_as[t] = as;
    g_ad[t] = ad;
}

// ---------------- K2 (fused): per-edge ex; atomic den; scatter ex*h[src] -----
__device__ __forceinline__ void red_add_v4(float* p, float a, float b2, float c, float d) {
    asm volatile("red.global.add.v4.f32 [%0], {%1, %2, %3, %4};"
                 :: "l"(p), "f"(a), "f"(b2), "f"(c), "f"(d) : "memory");
}

__global__ void k_edge_fused(const int* __restrict__ ei, const float* __restrict__ ea) {
    int idx = blockIdx.x * blockDim.x + threadIdx.x;
    if (idx >= BB * EE) return;
    int b = idx / EE;
    int e = idx - b * EE;
    const int* srcp = ei + (size_t)b * 2 * EE;
    const int* dstp = srcp + EE;
    int s = srcp[e];
    int d = dstp[e];

    float v = g_as[b * NN + s] + g_ad[b * NN + d] + g_ce * ea[(size_t)b * EE + e];
    v = (v > 0.0f) ? v : NEG_SLOPE * v;
    float ex = __expf(v);

    atomicAdd(&g_den[b * NN + d], ex);

    const float4* hp = reinterpret_cast<const float4*>(g_h + (size_t)(b * NN + s) * DEN);
    float* rp = g_rep + (size_t)(b * NN + d) * DEN;
#pragma unroll
    for (int u = 0; u < DEN / 4; u++) {
        float4 h4 = hp[u];
        red_add_v4(rp + u * 4, ex * h4.x, ex * h4.y, ex * h4.z, ex * h4.w);
    }

    // CSR row starts over sorted src (every regulator guaranteed covered)
    if (e == 0) {
        g_rowstart[b * (NREG + 1) + NREG] = EE;
        g_rowstart[b * (NREG + 1) + s] = 0;
    } else if (srcp[e - 1] != s) {
        g_rowstart[b * (NREG + 1) + s] = e;
    }
}

// ---------------- K3: per-node normalize + bias fold -------------------------
__global__ void k_norm(const float* __restrict__ bias) {
    int t = blockIdx.x * blockDim.x + threadIdx.x;
    if (t >= BB * NN) return;
    float den = g_den[t];
    float inv = (den > 0.0f) ? __frcp_rn(den) : 0.0f;
    float4* rp = reinterpret_cast<float4*>(g_rep + (size_t)t * DEN);
#pragma unroll
    for (int u = 0; u < DEN / 4; u++) {
        float4 r = rp[u];
        r.x = r.x * inv + __ldg(&bias[u * 4 + 0]);
        r.y = r.y * inv + __ldg(&bias[u * 4 + 1]);
        r.z = r.z * inv + __ldg(&bias[u * 4 + 2]);
        r.w = r.w * inv + __ldg(&bias[u * 4 + 3]);
        rp[u] = r;
    }
}

// ---------------- K4: warp-per-regulator, gather-on-insert dedup pool --------
#define POOL_WARPS 8
#define HSLOTS 256          // power of 2, >> max edges per regulator (~130)
#define DUPFLAG 0x40000000

__global__ void k_pool(const int* __restrict__ ei, float* __restrict__ out) {
    __shared__ int hkey[POOL_WARPS][HSLOTS];

    int warp = threadIdx.x >> 5;
    int lane = threadIdx.x & 31;
    int g = blockIdx.x * POOL_WARPS + warp;
    if (g >= BB * NREG) return;
    int b = g / NREG;
    int i = g - b * NREG;

    int s = g_rowstart[b * (NREG + 1) + i];
    int e = g_rowstart[b * (NREG + 1) + i + 1];
    int k = e - s;
    const int* dstp = ei + (size_t)b * 2 * EE + EE + s;

    // init hash
    for (int j = lane; j < HSLOTS; j += 32) hkey[warp][j] = -1;
    __syncwarp();

    // insert + gather in one pass:
    //   first occurrence of d  -> acc += rep[d]
    //   second occurrence      -> acc -= rep[d]   (net 0 for count>=2)
    //   further occurrences    -> 0
    float acc[DEN];
#pragma unroll
    for (int c = 0; c < DEN; c++) acc[c] = 0.0f;

    for (int j = lane; j < k; j += 32) {
        int d = dstp[j];
        unsigned slot = ((unsigned)d * 2654435761u >> 16) & (HSLOTS - 1);
        float sign = 0.0f;
        for (int probe = 0; probe < HSLOTS; probe++) {
            int prev = atomicCAS(&hkey[warp][slot], -1, d);
            if (prev == -1) { sign = 1.0f; break; }            // claimed (first)
            if ((prev & ~DUPFLAG) == d) {                      // same key -> duplicate
                int old = atomicOr(&hkey[warp][slot], DUPFLAG);
                sign = (old & DUPFLAG) ? 0.0f : -1.0f;         // only first dup subtracts
                break;
            }
            slot = (slot + 1) & (HSLOTS - 1);
        }
        if (sign != 0.0f) {
            const float4* rp = reinterpret_cast<const float4*>(g_rep + (size_t)(b * NN + d) * DEN);
#pragma unroll
            for (int u = 0; u < DEN / 4; u++) {
                float4 r = rp[u];
                acc[u * 4 + 0] += sign * r.x;
                acc[u * 4 + 1] += sign * r.y;
                acc[u * 4 + 2] += sign * r.z;
                acc[u * 4 + 3] += sign * r.w;
            }
        }
    }

    // warp reduction of 16 floats to lane 0
#pragma unroll
    for (int c = 0; c < DEN; c++)
#pragma unroll
        for (int off = 16; off > 0; off >>= 1)
            acc[c] += __shfl_down_sync(0xFFFFFFFFu, acc[c], off);

    if (lane == 0) {
        const float* rr = g_rep + (size_t)(b * NN + i) * DEN;   // regulator i == node i (rep incl. bias)
        float* op = out + (size_t)(b * NREG + i) * DEN;
#pragma unroll
        for (int c = 0; c < DEN; c++)
            op[c] = rr[c] * acc[c];
    }
}

// ---------------- launch ------------------------------------------------------
extern "C" void kernel_launch(void* const* d_in, const int* in_sizes, int n_in,
                              void* d_out, int out_size) {
    const float* fea      = (const float*)d_in[0];   // [B,N,64]
    const int*   ei       = (const int*)d_in[1];     // [B,2,E]
    const float* ea       = (const float*)d_in[2];   // [B,E,1]
    const float* W        = (const float*)d_in[3];   // [64,16]
    const float* att_src  = (const float*)d_in[4];   // [16]
    const float* att_dst  = (const float*)d_in[5];   // [16]
    const float* lin_edge = (const float*)d_in[6];   // [1,16]
    const float* att_edge = (const float*)d_in[7];   // [16]
    const float* bias     = (const float*)d_in[8];   // [16]
    float* out = (float*)d_out;                      // [B,NREG,16]

    (void)in_sizes; (void)n_in; (void)out_size;

    {
        int tot = BB * NN;
        k_node<<<(tot + 255) / 256, 256>>>(fea, W, att_src, att_dst, lin_edge, att_edge);
    }
    {
        int tot = BB * EE;
        k_edge_fused<<<(tot + 255) / 256, 256>>>(ei, ea);
    }
    {
        int tot = BB * NN;
        k_norm<<<(tot + 255) / 256, 256>>>(bias);
    }
    {
        int tot = BB * NREG;
        k_pool<<<(tot + POOL_WARPS - 1) / POOL_WARPS, POOL_WARPS * 32>>>(ei, out);
    }
}

// round 9
// speedup vs baseline: 1.1675x; 1.1675x over previous
#include <cuda_runtime.h>
#include <cstdint>

// Problem constants (fixed by the dataset)
#define BB 4
#define NN 10000
#define EE 163840
#define NREG 2000
#define DIN 64
#define DEN 16
#define NEG_SLOPE 0.2f

// ---------------- static device scratch (no allocations allowed) -------------
__device__ float g_h[BB * NN * DEN];              // h = x @ W
__device__ float g_as[BB * NN];                   // h @ att_src
__device__ float g_ad[BB * NN];                   // h @ att_dst
__device__ float g_den[BB * NN];                  // softmax denominator per dst
__device__ __align__(16) float g_rep[BB * NN * DEN]; // unnormalized then final rep
__device__ int   g_rowstart[BB * (NREG + 1)];     // CSR row starts over sorted src
__device__ float g_ce;                            // lin_edge . att_edge (scalar)

// ---------------- K1: per-node h = xW, a_s, a_d; zero den/rep; g_ce ----------
__global__ void k_node(const float* __restrict__ x, const float* __restrict__ W,
                       const float* __restrict__ att_s, const float* __restrict__ att_d,
                       const float* __restrict__ lin_edge, const float* __restrict__ att_edge) {
    __shared__ float Ws[DIN * DEN];
    for (int i = threadIdx.x; i < DIN * DEN; i += blockDim.x) Ws[i] = W[i];
    __syncthreads();

    int t = blockIdx.x * blockDim.x + threadIdx.x;
    if (t == 0) {
        float c = 0.0f;
#pragma unroll
        for (int j = 0; j < DEN; j++) c += lin_edge[j] * att_edge[j];
        g_ce = c;
    }
    if (t >= BB * NN) return;

    // zero the accumulators the edge pass will atomically update
    g_den[t] = 0.0f;
    float4* rz = reinterpret_cast<float4*>(g_rep + (size_t)t * DEN);
    float4 z4 = make_float4(0.f, 0.f, 0.f, 0.f);
#pragma unroll
    for (int u = 0; u < DEN / 4; u++) rz[u] = z4;

    const float4* xr = reinterpret_cast<const float4*>(x + (size_t)t * DIN);
    float acc[DEN];
#pragma unroll
    for (int c = 0; c < DEN; c++) acc[c] = 0.0f;

#pragma unroll
    for (int k4 = 0; k4 < DIN / 4; k4++) {
        float4 v = xr[k4];
        const float* w0 = &Ws[(k4 * 4 + 0) * DEN];
        const float* w1 = &Ws[(k4 * 4 + 1) * DEN];
        const float* w2 = &Ws[(k4 * 4 + 2) * DEN];
        const float* w3 = &Ws[(k4 * 4 + 3) * DEN];
#pragma unroll
        for (int c = 0; c < DEN; c++)
            acc[c] += v.x * w0[c] + v.y * w1[c] + v.z * w2[c] + v.w * w3[c];
    }

    float as = 0.0f, ad = 0.0f;
#pragma unroll
    for (int c = 0; c < DEN; c++) {
        as += acc[c] * __ldg(&att_s[c]);
        ad += acc[c] * __ldg(&att_d[c]);
    }

    float4* hp = reinterpret_cast<float4*>(g_h + (size_t)t * DEN);
#pragma unroll
    for (int u = 0; u < DEN / 4; u++)
        hp[u] = make_float4(acc[u * 4 + 0], acc[u * 4 + 1], acc[u * 4 + 2], acc[u * 4 + 3]);
    g_as[t] = as;
    g_ad[t] = ad;
}

// ---------------- K2 (fused): per-edge ex; atomic den; scatter ex*h[src] -----
__device__ __forceinline__ void red_add_v4(float* p, float a, float b2, float c, float d) {
    asm volatile("red.global.add.v4.f32 [%0], {%1, %2, %3, %4};"
                 :: "l"(p), "f"(a), "f"(b2), "f"(c), "f"(d) : "memory");
}

__global__ void k_edge_fused(const int* __restrict__ ei, const float* __restrict__ ea) {
    int idx = blockIdx.x * blockDim.x + threadIdx.x;
    if (idx >= BB * EE) return;
    int b = idx / EE;
    int e = idx - b * EE;
    const int* srcp = ei + (size_t)b * 2 * EE;
    const int* dstp = srcp + EE;
    int s = srcp[e];
    int d = dstp[e];

    float v = g_as[b * NN + s] + g_ad[b * NN + d] + g_ce * ea[(size_t)b * EE + e];
    v = (v > 0.0f) ? v : NEG_SLOPE * v;
    float ex = __expf(v);

    atomicAdd(&g_den[b * NN + d], ex);

    const float4* hp = reinterpret_cast<const float4*>(g_h + (size_t)(b * NN + s) * DEN);
    float* rp = g_rep + (size_t)(b * NN + d) * DEN;
#pragma unroll
    for (int u = 0; u < DEN / 4; u++) {
        float4 h4 = hp[u];
        red_add_v4(rp + u * 4, ex * h4.x, ex * h4.y, ex * h4.z, ex * h4.w);
    }

    // CSR row starts over sorted src (every regulator guaranteed covered)
    if (e == 0) {
        g_rowstart[b * (NREG + 1) + NREG] = EE;
        g_rowstart[b * (NREG + 1) + s] = 0;
    } else if (srcp[e - 1] != s) {
        g_rowstart[b * (NREG + 1) + s] = e;
    }
}

// ---------------- K3: per-node normalize + bias fold -------------------------
__global__ void k_norm(const float* __restrict__ bias) {
    int t = blockIdx.x * blockDim.x + threadIdx.x;
    if (t >= BB * NN) return;
    float den = g_den[t];
    float inv = (den > 0.0f) ? __frcp_rn(den) : 0.0f;
    float4* rp = reinterpret_cast<float4*>(g_rep + (size_t)t * DEN);
#pragma unroll
    for (int u = 0; u < DEN / 4; u++) {
        float4 r = rp[u];
        r.x = r.x * inv + __ldg(&bias[u * 4 + 0]);
        r.y = r.y * inv + __ldg(&bias[u * 4 + 1]);
        r.z = r.z * inv + __ldg(&bias[u * 4 + 2]);
        r.w = r.w * inv + __ldg(&bias[u * 4 + 3]);
        rp[u] = r;
    }
}

// ---------------- K4: warp-per-regulator hash dedup pool + output (R7) -------
#define POOL_WARPS 8
#define HSLOTS 256          // power of 2, >> max edges per regulator (~130)
#define DUPFLAG 0x40000000

__global__ void k_pool(const int* __restrict__ ei, float* __restrict__ out) {
    __shared__ int hkey[POOL_WARPS][HSLOTS];
    __shared__ int list[POOL_WARPS][HSLOTS];
    __shared__ int lcount[POOL_WARPS];

    int warp = threadIdx.x >> 5;
    int lane = threadIdx.x & 31;
    int g = blockIdx.x * POOL_WARPS + warp;
    if (g >= BB * NREG) return;
    int b = g / NREG;
    int i = g - b * NREG;

    int s = g_rowstart[b * (NREG + 1) + i];
    int e = g_rowstart[b * (NREG + 1) + i + 1];
    int k = e - s;
    const int* dstp = ei + (size_t)b * 2 * EE + EE + s;

    // init hash
    for (int j = lane; j < HSLOTS; j += 32) hkey[warp][j] = -1;
    if (lane == 0) lcount[warp] = 0;
    __syncwarp();

    // insert all dsts; flag duplicates (rare: E[dups] ~ 0.34/regulator)
    for (int j = lane; j < k; j += 32) {
        int d = dstp[j];
        unsigned slot = ((unsigned)d * 2654435761u >> 16) & (HSLOTS - 1);
        for (int probe = 0; probe < HSLOTS; probe++) {
            int prev = atomicCAS(&hkey[warp][slot], -1, d);
            if (prev == -1) break;                         // claimed
            if ((prev & ~DUPFLAG) == d) {                  // same key -> duplicate
                if (!(prev & DUPFLAG)) atomicOr(&hkey[warp][slot], DUPFLAG);
                break;
            }
            slot = (slot + 1) & (HSLOTS - 1);
        }
    }
    __syncwarp();

    // compact singleton keys (present, not flagged)
    for (int j = lane; j < HSLOTS; j += 32) {
        int h = hkey[warp][j];
        if (h >= 0 && !(h & DUPFLAG)) {
            int p = atomicAdd(&lcount[warp], 1);
            list[warp][p] = h;
        }
    }
    __syncwarp();
    int m = lcount[warp];

    // cooperative gather: 4 lanes per rep row (one float4 chunk each)
    int chunk = lane & 3;
    float4 acc = make_float4(0.f, 0.f, 0.f, 0.f);
    for (int idx = lane >> 2; idx < m; idx += 8) {
        int d = list[warp][idx];
        const float4* rp = reinterpret_cast<const float4*>(g_rep + (size_t)(b * NN + d) * DEN);
        float4 r = rp[chunk];
        acc.x += r.x; acc.y += r.y; acc.z += r.z; acc.w += r.w;
    }
    // reduce across the 8 lanes sharing each chunk id (strides 16, 8, 4)
#pragma unroll
    for (int off = 16; off >= 4; off >>= 1) {
        acc.x += __shfl_down_sync(0xFFFFFFFFu, acc.x, off);
        acc.y += __shfl_down_sync(0xFFFFFFFFu, acc.y, off);
        acc.z += __shfl_down_sync(0xFFFFFFFFu, acc.z, off);
        acc.w += __shfl_down_sync(0xFFFFFFFFu, acc.w, off);
    }

    if (lane < 4) {
        const float4* rr = reinterpret_cast<const float4*>(g_rep + (size_t)(b * NN + i) * DEN);
        float4 rv = rr[lane];   // regulator i == node i (rep already incl. bias)
        float4* op = reinterpret_cast<float4*>(out + (size_t)(b * NREG + i) * DEN);
        op[lane] = make_float4(rv.x * acc.x, rv.y * acc.y, rv.z * acc.z, rv.w * acc.w);
    }
}

// ---------------- launch ------------------------------------------------------
extern "C" void kernel_launch(void* const* d_in, const int* in_sizes, int n_in,
                              void* d_out, int out_size) {
    const float* fea      = (const float*)d_in[0];   // [B,N,64]
    const int*   ei       = (const int*)d_in[1];     // [B,2,E]
    const float* ea       = (const float*)d_in[2];   // [B,E,1]
    const float* W        = (const float*)d_in[3];   // [64,16]
    const float* att_src  = (const float*)d_in[4];   // [16]
    const float* att_dst  = (const float*)d_in[5];   // [16]
    const float* lin_edge = (const float*)d_in[6];   // [1,16]
    const float* att_edge = (const float*)d_in[7];   // [16]
    const float* bias     = (const float*)d_in[8];   // [16]
    float* out = (float*)d_out;                      // [B,NREG,16]

    (void)in_sizes; (void)n_in; (void)out_size;

    {
        int tot = BB * NN;
        k_node<<<(tot + 255) / 256, 256>>>(fea, W, att_src, att_dst, lin_edge, att_edge);
    }
    {
        int tot = BB * EE;
        k_edge_fused<<<(tot + 255) / 256, 256>>>(ei, ea);
    }
    {
        int tot = BB * NN;
        k_norm<<<(tot + 255) / 256, 256>>>(bias);
    }
    {
        int tot = BB * NREG;
        k_pool<<<(tot + POOL_WARPS - 1) / POOL_WARPS, POOL_WARPS * 32>>>(ei, out);
    }
}